// round 11
// baseline (speedup 1.0000x reference)
#include <cuda_runtime.h>
#include <math.h>

#define SR    16000
#define WIN   400
#define HOP   160
#define NFFT  512
#define NBIN  257
#define NMELS 40
#define NMFCC 13
#define BATCH 64
#define LEN   160000
#define NF    998
#define OUTC  39
#define NPAIR (BATCH * NF / 2)   // 31936 packed FFTs
#define GROUPS 2                 // FFT groups (64 thr each) per CTA
#define THREADS (GROUPS * 64)
#define NDCT  16                 // only mfcc[0..14] are ever needed
#define MAGSTRIDE 264            // compact magnitude layout stride (floats)

#ifndef M_PI
#define M_PI 3.14159265358979323846
#endif

// ---------------- constant tables (built by cheap init kernel each launch) ----------------
__device__ float d_window[WIN];
__device__ float d_fbw[NMELS * 33];   // packed sparse mel weights, stride 33 (zero-padded)
__device__ int   d_klo[NMELS];
__device__ int   d_flen[NMELS];
__device__ float d_dct16[NDCT * 41];  // first 16 DCT rows, stride 41 (zero-padded col 40)

__global__ void init_consts_kernel() {
    const int g  = blockIdx.x * blockDim.x + threadIdx.x;
    const int ng = gridDim.x * blockDim.x;
    const int t  = threadIdx.x;

    __shared__ double bins[NMELS + 2];
    if (t < NMELS + 2) {
        double high_mel = 2595.0 * log10(1.0 + (SR / 2.0) / 700.0);
        double mel = high_mel * ((double)t / (double)(NMELS + 1));
        double hz = 700.0 * (exp(mel * (2.302585092994045684 / 2595.0)) - 1.0);  // 10^x = e^{x ln10}
        bins[t] = floor((double)(NFFT + 1) * hz / (double)SR);
    }
    __syncthreads();

    for (int n = g; n < WIN; n += ng)
        d_window[n] = 0.54f - 0.46f * cosf((float)(2.0 * M_PI / (double)WIN) * (float)n);

    for (int i = g; i < NMELS * 33; i += ng) {
        int r = i / 33, j = i - r * 33;
        int lo = (int)bins[r], c = (int)bins[r + 1], hi = (int)bins[r + 2];
        int k = lo + j;
        float w = 0.0f;
        if (k < c)       w = (float)(k - lo) / (float)(c - lo);
        else if (k < hi) w = (float)(hi - k) / (float)(hi - c);
        d_fbw[i] = w;
    }
    if (g < NMELS) {
        int lo = (int)bins[g], hi = (int)bins[g + 2];
        d_klo[g] = lo;
        int len = hi - lo;
        d_flen[g] = len > 33 ? 33 : len;      // max actual width is 31
    }
    for (int i = g; i < NDCT * 41; i += ng) {
        int k = i / 41, n = i - k * 41;
        float val = 0.0f;
        if (n < NMELS) {
            float arg = (float)(M_PI / 80.0) * (float)(k * (2 * n + 1));
            float sc = (k == 0) ? 0.158113883008419f : 0.223606797749979f; // sqrt(1/40), sqrt(2/40)
            val = sc * cosf(arg);
        }
        d_dct16[i] = val;
    }
}

// ---------------- complex helpers ----------------
__device__ __forceinline__ float2 cadd(float2 a, float2 b) { return make_float2(a.x + b.x, a.y + b.y); }
__device__ __forceinline__ float2 csub(float2 a, float2 b) { return make_float2(a.x - b.x, a.y - b.y); }
__device__ __forceinline__ float2 cmul(float2 a, float2 b) {
    return make_float2(a.x * b.x - a.y * b.y, a.x * b.y + a.y * b.x);
}
__device__ __forceinline__ float2 negi(float2 a) { return make_float2(a.y, -a.x); }  // -i*a

__device__ __forceinline__ void dft8(float2 v[8]) {
    const float c = 0.70710678118654752f;
    float2 t0 = cadd(v[0], v[4]), t1 = csub(v[0], v[4]);
    float2 t2 = cadd(v[2], v[6]), t3 = csub(v[2], v[6]);
    float2 E0 = cadd(t0, t2), E2 = csub(t0, t2);
    float2 t3n = negi(t3);
    float2 E1 = cadd(t1, t3n), E3 = csub(t1, t3n);
    float2 u0 = cadd(v[1], v[5]), u1 = csub(v[1], v[5]);
    float2 u2 = cadd(v[3], v[7]), u3 = csub(v[3], v[7]);
    float2 O0 = cadd(u0, u2), O2 = csub(u0, u2);
    float2 u3n = negi(u3);
    float2 O1 = cadd(u1, u3n), O3 = csub(u1, u3n);
    O1 = make_float2(c * (O1.x + O1.y), c * (O1.y - O1.x));
    O2 = negi(O2);
    O3 = make_float2(c * (O3.y - O3.x), -c * (O3.x + O3.y));
    v[0] = cadd(E0, O0); v[4] = csub(E0, O0);
    v[1] = cadd(E1, O1); v[5] = csub(E1, O1);
    v[2] = cadd(E2, O2); v[6] = csub(E2, O2);
    v[3] = cadd(E3, O3); v[7] = csub(E3, O3);
}

// ---------------- main kernel: one frame-pair per 64-thread group ----------------
__global__ __launch_bounds__(THREADS, 10) void mfcc_kernel(const float* __restrict__ x,
                                                           float* __restrict__ out) {
    __shared__ float2 sZ[GROUPS][568];            // FFT exchange buffer; mag overlay
    __shared__ float  sMel[GROUPS][2][NMELS];
    __shared__ float  sFbw[NMELS * 33];
    __shared__ int    sKlo[NMELS];
    __shared__ int    sLen[NMELS];
    __shared__ float  sDct[NDCT * 41];

    const int tid = threadIdx.x;
    const int lt  = tid & 63;
    const int grp = tid >> 6;
    const int p   = blockIdx.x * GROUPS + grp;    // packed-pair id (grid exact)
    const int b   = p / (NF / 2);
    const int fp  = p - b * (NF / 2);
    const int f0  = 2 * fp;
    const size_t row = (size_t)b * LEN;
    const int base0 = f0 * HOP;

    // cooperative table staging (coalesced), CTA-wide; visibility covered by exchange-1 barrier
    for (int i = tid; i < NMELS * 33; i += THREADS) sFbw[i] = d_fbw[i];
    for (int i = tid; i < NDCT * 41;  i += THREADS) sDct[i] = d_dct16[i];
    if (tid < NMELS) { sKlo[tid] = d_klo[tid]; sLen[tid] = d_flen[tid]; }

    float2 v[8];

    // ---- load + pre-emphasis (prev via shfl) + window; f0 -> re, f0+1 -> im ----
    #pragma unroll
    for (int j = 0; j < 7; j++) {
        int n = lt + 64 * j;                      // covers all n < 448 >= WIN
        bool act = (n < WIN);
        int i0 = base0 + n;
        float a0 = act ? x[row + i0] : 0.0f;
        float a1 = act ? x[row + i0 + HOP] : 0.0f;
        float pr0 = __shfl_up_sync(0xffffffffu, a0, 1);
        float pr1 = __shfl_up_sync(0xffffffffu, a1, 1);
        if ((lt & 31) == 0) {                     // warp-boundary lanes load prev directly
            pr0 = (act && i0 > 0) ? x[row + i0 - 1] : 0.0f;
            pr1 = act ? x[row + i0 + HOP - 1] : 0.0f;
        }
        if (act) {
            float w = d_window[n];
            float p0 = (i0 == 0) ? a0 : (a0 - 0.97f * pr0);
            float p1 = a1 - 0.97f * pr1;
            v[j] = make_float2(p0 * w, p1 * w);
        } else {
            v[j] = make_float2(0.0f, 0.0f);
        }
    }
    v[7] = make_float2(0.0f, 0.0f);

    // ---- stage 1: radix-8 over stride 64, twiddle W512^(t*s) via sincos powers ----
    dft8(v);
    {
        float sv, cv;
        __sincosf(-0.01227184630308513f * (float)lt, &sv, &cv);   // -2*pi/512 * lt
        float2 w1 = make_float2(cv, sv);
        float2 w = w1;
        v[1] = cmul(v[1], w);
        #pragma unroll
        for (int s = 2; s < 8; s++) { w = cmul(w, w1); v[s] = cmul(v[s], w); }
    }

    // exchange 1: store z_s[t] at 72*s + t ; read z_s[n'' + 8j']
    #pragma unroll
    for (int s = 0; s < 8; s++) sZ[grp][72 * s + lt] = v[s];
    __syncthreads();
    {
        const int s = lt >> 3, npp = lt & 7;
        #pragma unroll
        for (int j = 0; j < 8; j++) v[j] = sZ[grp][72 * s + npp + 8 * j];
        __syncthreads();

        // ---- stage 2: radix-8, twiddle W64^(n''*s') ----
        dft8(v);
        {
            float sv, cv;
            __sincosf(-0.0981747704246810f * (float)npp, &sv, &cv); // -2*pi/64 * npp
            float2 w1 = make_float2(cv, sv);
            float2 w = w1;
            v[1] = cmul(v[1], w);
            #pragma unroll
            for (int sp = 2; sp < 8; sp++) { w = cmul(w, w1); v[sp] = cmul(v[sp], w); }
        }

        // exchange 2: store at 68*n'' + 8*s' + s (bank-bijective per half-warp)
        #pragma unroll
        for (int sp = 0; sp < 8; sp++) sZ[grp][68 * npp + 8 * sp + s] = v[sp];
    }
    __syncthreads();
    {
        const int sp = lt >> 3, s = lt & 7;       // outputs X[64m + 8sp + s] = X[64m + lt]
        #pragma unroll
        for (int j = 0; j < 8; j++) v[j] = sZ[grp][68 * j + 8 * sp + s];
        __syncthreads();

        // ---- stage 3: radix-8 -> store X flat at slot 64*m + lt ----
        dft8(v);
        #pragma unroll
        for (int m = 0; m < 8; m++) sZ[grp][64 * m + lt] = v[m];
    }
    __syncthreads();

    // ---- conjugate-symmetry unpack into registers, then compact stride-1 store ----
    float m0[4], m1[4];
    #pragma unroll
    for (int j = 0; j < 4; j++) {
        int k  = lt + 64 * j;                     // 0..255
        int kk = (NFFT - k) & (NFFT - 1);
        float2 u = sZ[grp][k];
        float2 w = sZ[grp][kk];
        float Ar = 0.5f * (u.x + w.x), Ai = 0.5f * (u.y - w.y);
        float Br = 0.5f * (u.y + w.y), Bi = 0.5f * (w.x - u.x);
        m0[j] = sqrtf(Ar * Ar + Ai * Ai);
        m1[j] = sqrtf(Br * Br + Bi * Bi);
    }
    float e0 = 0.0f, e1 = 0.0f;
    if (lt == 0) {                                // k = 256 (Nyquist)
        float2 u = sZ[grp][256];
        e0 = fabsf(u.x); e1 = fabsf(u.y);
    }
    __syncthreads();                              // all spectrum reads done
    float* __restrict__ sMagF = (float*)sZ[grp];  // overlay: mag0 at [k], mag1 at [264+k]
    #pragma unroll
    for (int j = 0; j < 4; j++) {
        int k = lt + 64 * j;
        sMagF[k] = m0[j];
        sMagF[MAGSTRIDE + k] = m1[j];
    }
    if (lt == 0) { sMagF[256] = e0; sMagF[MAGSTRIDE + 256] = e1; }
    __syncthreads();

    // ---- mel filterbank + log (80 tasks over 64 threads), variable-length ----
    #pragma unroll
    for (int i = lt; i < 2 * NMELS; i += 64) {
        int fr = i / NMELS, m = i - fr * NMELS;
        const int klo = sKlo[m], len = sLen[m];
        const float* __restrict__ fw = sFbw + m * 33;
        const float* __restrict__ mg = sMagF + fr * MAGSTRIDE + klo;
        float acc = 0.0f;
        for (int j = 0; j < len; j++) acc = fmaf(fw[j], mg[j], acc);
        sMel[grp][fr][m] = __logf(acc + 1e-20f);
    }
    __syncthreads();

    // ---- DCT-II (16 rows, pair-split) + deltas + store: all warp-local via shuffles ----
    // warp 0 of group handles fr=0 (tasks m=0..15 on lane pairs), warp 1 handles fr=1.
    {
        const int half = lt & 1;
        const int m    = (lt & 31) >> 1;          // 0..15
        const int fr   = lt >> 5;                 // == warp id within group
        const float* __restrict__ dr = sDct + m * 41 + half * 20;
        const float* __restrict__ ml = sMel[grp][fr] + half * 20;
        float acc = 0.0f;
        #pragma unroll
        for (int n = 0; n < 20; n++) acc = fmaf(dr[n], ml[n], acc);
        acc += __shfl_xor_sync(0xffffffffu, acc, 1);   // mfcc[fr][m] in both pair lanes

        // d1[m] = 0.5*(mfcc[m+1]-mfcc[m-1]) for 1<=m<=14 (else 0)
        float up = __shfl_down_sync(0xffffffffu, acc, 2);
        float dn = __shfl_up_sync(0xffffffffu, acc, 2);
        float d1 = (m >= 1 && m <= 14) ? 0.5f * (up - dn) : 0.0f;

        // d2[m] = 0.5*(d1[m+1]-d1[m-1]) for m>=1 (needed only m<=12; d1[13] valid)
        float u2 = __shfl_down_sync(0xffffffffu, d1, 2);
        float l2 = __shfl_up_sync(0xffffffffu, d1, 2);
        float d2 = (m >= 1) ? 0.5f * (u2 - l2) : 0.0f;

        if (half == 0 && m < NMFCC) {
            float* __restrict__ ob = out + (size_t)(b * NF + f0 + fr) * OUTC;
            ob[m]             = acc;
            ob[NMFCC + m]     = d1;
            ob[2 * NMFCC + m] = d2;
        }
    }
}

extern "C" void kernel_launch(void* const* d_in, const int* in_sizes, int n_in,
                              void* d_out, int out_size) {
    (void)in_sizes; (void)n_in; (void)out_size;
    const float* x = (const float*)d_in[0];
    float* out = (float*)d_out;
    init_consts_kernel<<<8, 128>>>();
    mfcc_kernel<<<NPAIR / GROUPS, THREADS>>>(x, out);
}

// round 12
// speedup vs baseline: 1.0191x; 1.0191x over previous
#include <cuda_runtime.h>
#include <math.h>

#define SR    16000
#define WIN   400
#define HOP   160
#define NFFT  512
#define NBIN  257
#define NMELS 40
#define NMFCC 13
#define BATCH 64
#define LEN   160000
#define NF    998
#define OUTC  39
#define NPAIR (BATCH * NF / 2)   // 31936 packed FFTs
#define GROUPS 2                 // FFT groups (64 thr each) per CTA
#define THREADS (GROUPS * 64)
#define NDCT  16                 // only mfcc[0..14] are ever needed
#define MAGSTRIDE 264            // compact magnitude layout stride (floats)

#ifndef M_PI
#define M_PI 3.14159265358979323846
#endif

// ---------------- constant tables (built by cheap init kernel each launch) ----------------
__device__ float d_window[WIN];
__device__ float d_fbw[NMELS * 33];   // packed sparse mel weights, stride 33 (zero-padded)
__device__ int   d_klo[NMELS];
__device__ int   d_flen[NMELS];
__device__ float d_dct16[NDCT * 41];  // first 16 DCT rows, stride 41 (zero-padded col 40)

__global__ void init_consts_kernel() {
    const int g  = blockIdx.x * blockDim.x + threadIdx.x;
    const int ng = gridDim.x * blockDim.x;
    const int t  = threadIdx.x;

    __shared__ double bins[NMELS + 2];
    if (t < NMELS + 2) {
        double high_mel = 2595.0 * log10(1.0 + (SR / 2.0) / 700.0);
        double mel = high_mel * ((double)t / (double)(NMELS + 1));
        double hz = 700.0 * (exp(mel * (2.302585092994045684 / 2595.0)) - 1.0);  // 10^x = e^{x ln10}
        bins[t] = floor((double)(NFFT + 1) * hz / (double)SR);
    }
    __syncthreads();

    for (int n = g; n < WIN; n += ng)
        d_window[n] = 0.54f - 0.46f * cosf((float)(2.0 * M_PI / (double)WIN) * (float)n);

    for (int i = g; i < NMELS * 33; i += ng) {
        int r = i / 33, j = i - r * 33;
        int lo = (int)bins[r], c = (int)bins[r + 1], hi = (int)bins[r + 2];
        int k = lo + j;
        float w = 0.0f;
        if (k < c)       w = (float)(k - lo) / (float)(c - lo);
        else if (k < hi) w = (float)(hi - k) / (float)(hi - c);
        d_fbw[i] = w;
    }
    if (g < NMELS) {
        int lo = (int)bins[g], hi = (int)bins[g + 2];
        d_klo[g] = lo;
        int len = hi - lo;
        d_flen[g] = len > 33 ? 33 : len;      // max actual width is 31
    }
    for (int i = g; i < NDCT * 41; i += ng) {
        int k = i / 41, n = i - k * 41;
        float val = 0.0f;
        if (n < NMELS) {
            float arg = (float)(M_PI / 80.0) * (float)(k * (2 * n + 1));
            float sc = (k == 0) ? 0.158113883008419f : 0.223606797749979f; // sqrt(1/40), sqrt(2/40)
            val = sc * cosf(arg);
        }
        d_dct16[i] = val;
    }
}

// ---------------- complex helpers ----------------
__device__ __forceinline__ float2 cadd(float2 a, float2 b) { return make_float2(a.x + b.x, a.y + b.y); }
__device__ __forceinline__ float2 csub(float2 a, float2 b) { return make_float2(a.x - b.x, a.y - b.y); }
__device__ __forceinline__ float2 cmul(float2 a, float2 b) {
    return make_float2(a.x * b.x - a.y * b.y, a.x * b.y + a.y * b.x);
}
__device__ __forceinline__ float2 negi(float2 a) { return make_float2(a.y, -a.x); }  // -i*a

__device__ __forceinline__ void dft8(float2 v[8]) {
    const float c = 0.70710678118654752f;
    float2 t0 = cadd(v[0], v[4]), t1 = csub(v[0], v[4]);
    float2 t2 = cadd(v[2], v[6]), t3 = csub(v[2], v[6]);
    float2 E0 = cadd(t0, t2), E2 = csub(t0, t2);
    float2 t3n = negi(t3);
    float2 E1 = cadd(t1, t3n), E3 = csub(t1, t3n);
    float2 u0 = cadd(v[1], v[5]), u1 = csub(v[1], v[5]);
    float2 u2 = cadd(v[3], v[7]), u3 = csub(v[3], v[7]);
    float2 O0 = cadd(u0, u2), O2 = csub(u0, u2);
    float2 u3n = negi(u3);
    float2 O1 = cadd(u1, u3n), O3 = csub(u1, u3n);
    O1 = make_float2(c * (O1.x + O1.y), c * (O1.y - O1.x));
    O2 = negi(O2);
    O3 = make_float2(c * (O3.y - O3.x), -c * (O3.x + O3.y));
    v[0] = cadd(E0, O0); v[4] = csub(E0, O0);
    v[1] = cadd(E1, O1); v[5] = csub(E1, O1);
    v[2] = cadd(E2, O2); v[6] = csub(E2, O2);
    v[3] = cadd(E3, O3); v[7] = csub(E3, O3);
}

// ---------------- main kernel: one frame-pair per 64-thread group ----------------
__global__ __launch_bounds__(THREADS, 10) void mfcc_kernel(const float* __restrict__ x,
                                                           float* __restrict__ out) {
    __shared__ float2 sZ[GROUPS][568];            // FFT exchange buffer; mag overlay
    __shared__ float  sMel[GROUPS][2][NMELS];
    __shared__ float  sFbw[NMELS * 33];
    __shared__ int    sKlo[NMELS];
    __shared__ int    sLen[NMELS];
    __shared__ float  sDct[NDCT * 41];

    const int tid = threadIdx.x;
    const int lt  = tid & 63;
    const int grp = tid >> 6;
    const int p   = blockIdx.x * GROUPS + grp;    // packed-pair id (grid exact)
    const int b   = p / (NF / 2);
    const int fp  = p - b * (NF / 2);
    const int f0  = 2 * fp;
    const size_t row = (size_t)b * LEN;
    const int base0 = f0 * HOP;

    // cooperative table staging (coalesced), CTA-wide; visibility covered by exchange-1 barrier
    for (int i = tid; i < NMELS * 33; i += THREADS) sFbw[i] = d_fbw[i];
    for (int i = tid; i < NDCT * 41;  i += THREADS) sDct[i] = d_dct16[i];
    if (tid < NMELS) { sKlo[tid] = d_klo[tid]; sLen[tid] = d_flen[tid]; }

    float2 v[8];

    // ---- load + pre-emphasis + window (direct dual LDG; coalesced & line-shared) ----
    #pragma unroll
    for (int j = 0; j < 8; j++) {
        int n = lt + 64 * j;
        if (n < WIN) {
            float w = d_window[n];
            int i0 = base0 + n;
            float a0 = x[row + i0];
            float p0 = (i0 == 0) ? a0 : (a0 - 0.97f * x[row + i0 - 1]);
            int i1 = i0 + HOP;
            float a1 = x[row + i1];
            float p1 = a1 - 0.97f * x[row + i1 - 1];
            v[j] = make_float2(p0 * w, p1 * w);
        } else {
            v[j] = make_float2(0.0f, 0.0f);
        }
    }

    // ---- stage 1: radix-8 over stride 64, twiddle W512^(t*s) via sincos powers ----
    dft8(v);
    {
        float sv, cv;
        __sincosf(-0.01227184630308513f * (float)lt, &sv, &cv);   // -2*pi/512 * lt
        float2 w1 = make_float2(cv, sv);
        float2 w = w1;
        v[1] = cmul(v[1], w);
        #pragma unroll
        for (int s = 2; s < 8; s++) { w = cmul(w, w1); v[s] = cmul(v[s], w); }
    }

    // exchange 1: store z_s[t] at 72*s + t ; read z_s[n'' + 8j']
    #pragma unroll
    for (int s = 0; s < 8; s++) sZ[grp][72 * s + lt] = v[s];
    __syncthreads();
    {
        const int s = lt >> 3, npp = lt & 7;
        #pragma unroll
        for (int j = 0; j < 8; j++) v[j] = sZ[grp][72 * s + npp + 8 * j];
        __syncthreads();

        // ---- stage 2: radix-8, twiddle W64^(n''*s') ----
        dft8(v);
        {
            float sv, cv;
            __sincosf(-0.0981747704246810f * (float)npp, &sv, &cv); // -2*pi/64 * npp
            float2 w1 = make_float2(cv, sv);
            float2 w = w1;
            v[1] = cmul(v[1], w);
            #pragma unroll
            for (int sp = 2; sp < 8; sp++) { w = cmul(w, w1); v[sp] = cmul(v[sp], w); }
        }

        // exchange 2: store at 68*n'' + 8*s' + s (bank-bijective per half-warp)
        #pragma unroll
        for (int sp = 0; sp < 8; sp++) sZ[grp][68 * npp + 8 * sp + s] = v[sp];
    }
    __syncthreads();
    {
        const int sp = lt >> 3, s = lt & 7;       // outputs X[64m + 8sp + s] = X[64m + lt]
        #pragma unroll
        for (int j = 0; j < 8; j++) v[j] = sZ[grp][68 * j + 8 * sp + s];
        __syncthreads();

        // ---- stage 3: radix-8 -> store X flat at slot 64*m + lt ----
        dft8(v);
        #pragma unroll
        for (int m = 0; m < 8; m++) sZ[grp][64 * m + lt] = v[m];
    }
    __syncthreads();

    // ---- conjugate-symmetry unpack into registers, then compact stride-1 store ----
    float m0[4], m1[4];
    #pragma unroll
    for (int j = 0; j < 4; j++) {
        int k  = lt + 64 * j;                     // 0..255
        int kk = (NFFT - k) & (NFFT - 1);
        float2 u = sZ[grp][k];
        float2 w = sZ[grp][kk];
        float Ar = 0.5f * (u.x + w.x), Ai = 0.5f * (u.y - w.y);
        float Br = 0.5f * (u.y + w.y), Bi = 0.5f * (w.x - u.x);
        m0[j] = sqrtf(Ar * Ar + Ai * Ai);
        m1[j] = sqrtf(Br * Br + Bi * Bi);
    }
    float e0 = 0.0f, e1 = 0.0f;
    if (lt == 0) {                                // k = 256 (Nyquist)
        float2 u = sZ[grp][256];
        e0 = fabsf(u.x); e1 = fabsf(u.y);
    }
    __syncthreads();                              // all spectrum reads done
    float* __restrict__ sMagF = (float*)sZ[grp];  // overlay: mag0 at [k], mag1 at [264+k]
    #pragma unroll
    for (int j = 0; j < 4; j++) {
        int k = lt + 64 * j;
        sMagF[k] = m0[j];
        sMagF[MAGSTRIDE + k] = m1[j];
    }
    if (lt == 0) { sMagF[256] = e0; sMagF[MAGSTRIDE + 256] = e1; }
    __syncthreads();

    // ---- mel filterbank + log (80 tasks over 64 threads), variable-length ----
    #pragma unroll
    for (int i = lt; i < 2 * NMELS; i += 64) {
        int fr = i / NMELS, m = i - fr * NMELS;
        const int klo = sKlo[m], len = sLen[m];
        const float* __restrict__ fw = sFbw + m * 33;
        const float* __restrict__ mg = sMagF + fr * MAGSTRIDE + klo;
        float acc = 0.0f;
        for (int j = 0; j < len; j++) acc = fmaf(fw[j], mg[j], acc);
        sMel[grp][fr][m] = __logf(acc + 1e-20f);
    }
    __syncthreads();

    // ---- DCT-II (16 rows, pair-split) + deltas + store: all warp-local via shuffles ----
    // warp 0 of group handles fr=0 (tasks m=0..15 on lane pairs), warp 1 handles fr=1.
    {
        const int half = lt & 1;
        const int m    = (lt & 31) >> 1;          // 0..15
        const int fr   = lt >> 5;                 // == warp id within group
        const float* __restrict__ dr = sDct + m * 41 + half * 20;
        const float* __restrict__ ml = sMel[grp][fr] + half * 20;
        float acc = 0.0f;
        #pragma unroll
        for (int n = 0; n < 20; n++) acc = fmaf(dr[n], ml[n], acc);
        acc += __shfl_xor_sync(0xffffffffu, acc, 1);   // mfcc[fr][m] in both pair lanes

        // d1[m] = 0.5*(mfcc[m+1]-mfcc[m-1]) for 1<=m<=14 (else 0)
        float up = __shfl_down_sync(0xffffffffu, acc, 2);
        float dn = __shfl_up_sync(0xffffffffu, acc, 2);
        float d1 = (m >= 1 && m <= 14) ? 0.5f * (up - dn) : 0.0f;

        // d2[m] = 0.5*(d1[m+1]-d1[m-1]) for m>=1 (needed only m<=12; d1[13] valid)
        float u2 = __shfl_down_sync(0xffffffffu, d1, 2);
        float l2 = __shfl_up_sync(0xffffffffu, d1, 2);
        float d2 = (m >= 1) ? 0.5f * (u2 - l2) : 0.0f;

        if (half == 0 && m < NMFCC) {
            float* __restrict__ ob = out + (size_t)(b * NF + f0 + fr) * OUTC;
            ob[m]             = acc;
            ob[NMFCC + m]     = d1;
            ob[2 * NMFCC + m] = d2;
        }
    }
}

extern "C" void kernel_launch(void* const* d_in, const int* in_sizes, int n_in,
                              void* d_out, int out_size) {
    (void)in_sizes; (void)n_in; (void)out_size;
    const float* x = (const float*)d_in[0];
    float* out = (float*)d_out;
    init_consts_kernel<<<8, 128>>>();
    mfcc_kernel<<<NPAIR / GROUPS, THREADS>>>(x, out);
}

// round 13
// speedup vs baseline: 1.0218x; 1.0027x over previous
#include <cuda_runtime.h>
#include <math.h>

#define SR    16000
#define WIN   400
#define HOP   160
#define NFFT  512
#define NBIN  257
#define NMELS 40
#define NMFCC 13
#define BATCH 64
#define LEN   160000
#define NF    998
#define OUTC  39
#define NPAIR (BATCH * NF / 2)   // 31936 packed FFTs
#define GROUPS 2                 // FFT groups (64 thr each) per CTA
#define THREADS (GROUPS * 64)
#define NDCT  16                 // only mfcc[0..14] are ever needed
#define MAGSTRIDE 264            // magnitude layout stride (floats)
#define MAGBASE 1024             // float offset of mag region inside sZ (past spectrum)

#ifndef M_PI
#define M_PI 3.14159265358979323846
#endif

// ---------------- constant tables (built by cheap init kernel each launch) ----------------
__device__ float d_window[WIN];
__device__ float d_fbw[NMELS * 33];   // packed sparse mel weights, stride 33 (zero-padded)
__device__ int   d_klo[NMELS];
__device__ int   d_flen[NMELS];
__device__ float d_dct16[NDCT * 41];  // first 16 DCT rows, stride 41 (zero-padded col 40)

__global__ void init_consts_kernel() {
    const int g  = blockIdx.x * blockDim.x + threadIdx.x;
    const int ng = gridDim.x * blockDim.x;
    const int t  = threadIdx.x;

    __shared__ double bins[NMELS + 2];
    if (t < NMELS + 2) {
        double high_mel = 2595.0 * log10(1.0 + (SR / 2.0) / 700.0);
        double mel = high_mel * ((double)t / (double)(NMELS + 1));
        double hz = 700.0 * (exp(mel * (2.302585092994045684 / 2595.0)) - 1.0);  // 10^x = e^{x ln10}
        bins[t] = floor((double)(NFFT + 1) * hz / (double)SR);
    }
    __syncthreads();

    for (int n = g; n < WIN; n += ng)
        d_window[n] = 0.54f - 0.46f * cosf((float)(2.0 * M_PI / (double)WIN) * (float)n);

    for (int i = g; i < NMELS * 33; i += ng) {
        int r = i / 33, j = i - r * 33;
        int lo = (int)bins[r], c = (int)bins[r + 1], hi = (int)bins[r + 2];
        int k = lo + j;
        float w = 0.0f;
        if (k < c)       w = (float)(k - lo) / (float)(c - lo);
        else if (k < hi) w = (float)(hi - k) / (float)(hi - c);
        d_fbw[i] = w;
    }
    if (g < NMELS) {
        int lo = (int)bins[g], hi = (int)bins[g + 2];
        d_klo[g] = lo;
        int len = hi - lo;
        d_flen[g] = len > 33 ? 33 : len;      // max actual width is 31
    }
    for (int i = g; i < NDCT * 41; i += ng) {
        int k = i / 41, n = i - k * 41;
        float val = 0.0f;
        if (n < NMELS) {
            float arg = (float)(M_PI / 80.0) * (float)(k * (2 * n + 1));
            float sc = (k == 0) ? 0.158113883008419f : 0.223606797749979f; // sqrt(1/40), sqrt(2/40)
            val = sc * cosf(arg);
        }
        d_dct16[i] = val;
    }
}

// ---------------- complex helpers ----------------
__device__ __forceinline__ float2 cadd(float2 a, float2 b) { return make_float2(a.x + b.x, a.y + b.y); }
__device__ __forceinline__ float2 csub(float2 a, float2 b) { return make_float2(a.x - b.x, a.y - b.y); }
__device__ __forceinline__ float2 cmul(float2 a, float2 b) {
    return make_float2(a.x * b.x - a.y * b.y, a.x * b.y + a.y * b.x);
}
__device__ __forceinline__ float2 negi(float2 a) { return make_float2(a.y, -a.x); }  // -i*a

__device__ __forceinline__ void dft8(float2 v[8]) {
    const float c = 0.70710678118654752f;
    float2 t0 = cadd(v[0], v[4]), t1 = csub(v[0], v[4]);
    float2 t2 = cadd(v[2], v[6]), t3 = csub(v[2], v[6]);
    float2 E0 = cadd(t0, t2), E2 = csub(t0, t2);
    float2 t3n = negi(t3);
    float2 E1 = cadd(t1, t3n), E3 = csub(t1, t3n);
    float2 u0 = cadd(v[1], v[5]), u1 = csub(v[1], v[5]);
    float2 u2 = cadd(v[3], v[7]), u3 = csub(v[3], v[7]);
    float2 O0 = cadd(u0, u2), O2 = csub(u0, u2);
    float2 u3n = negi(u3);
    float2 O1 = cadd(u1, u3n), O3 = csub(u1, u3n);
    O1 = make_float2(c * (O1.x + O1.y), c * (O1.y - O1.x));
    O2 = negi(O2);
    O3 = make_float2(c * (O3.y - O3.x), -c * (O3.x + O3.y));
    v[0] = cadd(E0, O0); v[4] = csub(E0, O0);
    v[1] = cadd(E1, O1); v[5] = csub(E1, O1);
    v[2] = cadd(E2, O2); v[6] = csub(E2, O2);
    v[3] = cadd(E3, O3); v[7] = csub(E3, O3);
}

// ---------------- main kernel: one frame-pair per 64-thread group ----------------
__global__ __launch_bounds__(THREADS, 10) void mfcc_kernel(const float* __restrict__ x,
                                                           float* __restrict__ out) {
    __shared__ float2 sZ[GROUPS][776];            // FFT exchange (<=568) + disjoint mag region
    __shared__ float  sMel[GROUPS][2][NMELS];
    __shared__ float  sMfcc[GROUPS][2][NDCT];
    __shared__ float  sD1[GROUPS][2][NDCT];
    __shared__ float  sFbw[NMELS * 33];
    __shared__ int    sKlo[NMELS];
    __shared__ int    sLen[NMELS];
    __shared__ float  sDct[NDCT * 41];

    const int tid = threadIdx.x;
    const int lt  = tid & 63;
    const int grp = tid >> 6;
    const int p   = blockIdx.x * GROUPS + grp;    // packed-pair id (grid exact)
    const int b   = p / (NF / 2);
    const int fp  = p - b * (NF / 2);
    const int f0  = 2 * fp;
    const size_t row = (size_t)b * LEN;
    const int base0 = f0 * HOP;

    // cooperative table staging (coalesced); visibility covered by exchange-1 barrier
    for (int i = tid; i < NMELS * 33; i += THREADS) sFbw[i] = d_fbw[i];
    for (int i = tid; i < NDCT * 41;  i += THREADS) sDct[i] = d_dct16[i];
    if (tid < NMELS) { sKlo[tid] = d_klo[tid]; sLen[tid] = d_flen[tid]; }

    float2 v[8];

    // ---- load + pre-emphasis + window (direct dual LDG; coalesced & line-shared) ----
    #pragma unroll
    for (int j = 0; j < 8; j++) {
        int n = lt + 64 * j;
        if (n < WIN) {
            float w = d_window[n];
            int i0 = base0 + n;
            float a0 = x[row + i0];
            float p0 = (i0 == 0) ? a0 : (a0 - 0.97f * x[row + i0 - 1]);
            int i1 = i0 + HOP;
            float a1 = x[row + i1];
            float p1 = a1 - 0.97f * x[row + i1 - 1];
            v[j] = make_float2(p0 * w, p1 * w);
        } else {
            v[j] = make_float2(0.0f, 0.0f);
        }
    }

    // ---- stage 1: radix-8 over stride 64, twiddle W512^(t*s) via sincos powers ----
    dft8(v);
    {
        float sv, cv;
        __sincosf(-0.01227184630308513f * (float)lt, &sv, &cv);   // -2*pi/512 * lt
        float2 w1 = make_float2(cv, sv);
        float2 w = w1;
        v[1] = cmul(v[1], w);
        #pragma unroll
        for (int s = 2; s < 8; s++) { w = cmul(w, w1); v[s] = cmul(v[s], w); }
    }

    // exchange 1: store z_s[t] at 72*s + t ; read z_s[n'' + 8j']
    #pragma unroll
    for (int s = 0; s < 8; s++) sZ[grp][72 * s + lt] = v[s];
    __syncthreads();
    {
        const int s = lt >> 3, npp = lt & 7;
        #pragma unroll
        for (int j = 0; j < 8; j++) v[j] = sZ[grp][72 * s + npp + 8 * j];
        __syncthreads();

        // ---- stage 2: radix-8, twiddle W64^(n''*s') ----
        dft8(v);
        {
            float sv, cv;
            __sincosf(-0.0981747704246810f * (float)npp, &sv, &cv); // -2*pi/64 * npp
            float2 w1 = make_float2(cv, sv);
            float2 w = w1;
            v[1] = cmul(v[1], w);
            #pragma unroll
            for (int sp = 2; sp < 8; sp++) { w = cmul(w, w1); v[sp] = cmul(v[sp], w); }
        }

        // exchange 2: store at 68*n'' + 8*s' + s (bank-bijective per half-warp)
        #pragma unroll
        for (int sp = 0; sp < 8; sp++) sZ[grp][68 * npp + 8 * sp + s] = v[sp];
    }
    __syncthreads();
    {
        const int sp = lt >> 3, s = lt & 7;       // outputs X[64m + 8sp + s] = X[64m + lt]
        #pragma unroll
        for (int j = 0; j < 8; j++) v[j] = sZ[grp][68 * j + 8 * sp + s];
        __syncthreads();

        // ---- stage 3: radix-8 -> store X flat at slot 64*m + lt ----
        dft8(v);
        #pragma unroll
        for (int m = 0; m < 8; m++) sZ[grp][64 * m + lt] = v[m];
    }
    __syncthreads();

    // ---- conjugate-symmetry unpack -> mags written to DISJOINT region (no barrier) ----
    // spectrum occupies float2 slots 0..511 (floats 0..1023); mags at floats 1024.. -> no alias.
    float* __restrict__ sMagF = (float*)sZ[grp] + MAGBASE;   // mag0 at [k], mag1 at [264+k]
    #pragma unroll
    for (int j = 0; j < 4; j++) {
        int k  = lt + 64 * j;                     // 0..255
        int kk = (NFFT - k) & (NFFT - 1);
        float2 u = sZ[grp][k];
        float2 w = sZ[grp][kk];
        float Ar = 0.5f * (u.x + w.x), Ai = 0.5f * (u.y - w.y);
        float Br = 0.5f * (u.y + w.y), Bi = 0.5f * (w.x - u.x);
        sMagF[k]             = sqrtf(Ar * Ar + Ai * Ai);
        sMagF[MAGSTRIDE + k] = sqrtf(Br * Br + Bi * Bi);
    }
    if (lt == 0) {                                // k = 256 (Nyquist): X real/imag split
        float2 u = sZ[grp][256];
        sMagF[256]             = fabsf(u.x);
        sMagF[MAGSTRIDE + 256] = fabsf(u.y);
    }
    __syncthreads();                              // mags visible to both warps

    // ---- mel filterbank + log (80 tasks over 64 threads), variable-length ----
    #pragma unroll
    for (int i = lt; i < 2 * NMELS; i += 64) {
        int fr = i / NMELS, m = i - fr * NMELS;
        const int klo = sKlo[m], len = sLen[m];
        const float* __restrict__ fw = sFbw + m * 33;
        const float* __restrict__ mg = sMagF + fr * MAGSTRIDE + klo;
        float acc = 0.0f;
        for (int j = 0; j < len; j++) acc = fmaf(fw[j], mg[j], acc);
        sMel[grp][fr][m] = __logf(acc + 1e-20f);
    }
    __syncthreads();

    // ---- DCT-II ortho, 16 rows, split dot across thread pairs ----
    {
        int task = lt >> 1;                       // 0..31 = (fr, m)
        int half = lt & 1;
        int fr = task >> 4, m = task & 15;
        const float* __restrict__ dr = sDct + m * 41 + half * 20;
        const float* __restrict__ ml = sMel[grp][fr] + half * 20;
        float acc = 0.0f;
        #pragma unroll
        for (int n = 0; n < 20; n++) acc = fmaf(dr[n], ml[n], acc);
        acc += __shfl_xor_sync(0xffffffffu, acc, 1);
        if (half == 0) sMfcc[grp][fr][m] = acc;
    }
    __syncthreads();

    // ---- first delta over coefficients (valid for c<=14; we need c<=13) ----
    if (lt < 32) {
        int fr = lt >> 4, c = lt & 15;
        float val = 0.0f;
        if (c >= 1 && c <= 14) val = 0.5f * (sMfcc[grp][fr][c + 1] - sMfcc[grp][fr][c - 1]);
        sD1[grp][fr][c] = val;
    }
    __syncthreads();

    // ---- write [mfcc[0:13], d1[0:13], d2[0:13]] for both frames ----
    #pragma unroll
    for (int i = lt; i < 2 * OUTC; i += 64) {
        int fr = i / OUTC, c = i - fr * OUTC;
        int frame = b * NF + f0 + fr;
        float val;
        if (c < NMFCC) {
            val = sMfcc[grp][fr][c];
        } else if (c < 2 * NMFCC) {
            val = sD1[grp][fr][c - NMFCC];
        } else {
            int cc = c - 2 * NMFCC;
            val = (cc >= 1) ? 0.5f * (sD1[grp][fr][cc + 1] - sD1[grp][fr][cc - 1]) : 0.0f;
        }
        out[(size_t)frame * OUTC + c] = val;
    }
}

extern "C" void kernel_launch(void* const* d_in, const int* in_sizes, int n_in,
                              void* d_out, int out_size) {
    (void)in_sizes; (void)n_in; (void)out_size;
    const float* x = (const float*)d_in[0];
    float* out = (float*)d_out;
    init_consts_kernel<<<8, 128>>>();
    mfcc_kernel<<<NPAIR / GROUPS, THREADS>>>(x, out);
}

// round 14
// speedup vs baseline: 1.0834x; 1.0603x over previous
#include <cuda_runtime.h>
#include <math.h>

#define SR    16000
#define WIN   400
#define HOP   160
#define NFFT  512
#define NBIN  257
#define NMELS 40
#define NMFCC 13
#define BATCH 64
#define LEN   160000
#define NF    998
#define OUTC  39
#define NPAIR (BATCH * NF / 2)   // 31936 packed FFTs
#define GROUPS 4                 // FFT groups (64 thr each) per CTA
#define THREADS (GROUPS * 64)
#define NDCT  16                 // only mfcc[0..14] are ever needed
#define MAGSTRIDE 264            // compact magnitude layout stride (floats)

#ifndef M_PI
#define M_PI 3.14159265358979323846
#endif

// ---------------- constant tables (built by cheap init kernel each launch) ----------------
__device__ float d_window[WIN];
__device__ float d_fbw[NMELS * 33];   // packed sparse mel weights, stride 33 (zero-padded)
__device__ int   d_klo[NMELS];
__device__ int   d_flen[NMELS];
__device__ float d_dct16[NDCT * 41];  // first 16 DCT rows, stride 41 (zero-padded col 40)

__global__ void init_consts_kernel() {
    const int g  = blockIdx.x * blockDim.x + threadIdx.x;
    const int ng = gridDim.x * blockDim.x;
    const int t  = threadIdx.x;

    __shared__ double bins[NMELS + 2];
    if (t < NMELS + 2) {
        double high_mel = 2595.0 * log10(1.0 + (SR / 2.0) / 700.0);
        double mel = high_mel * ((double)t / (double)(NMELS + 1));
        double hz = 700.0 * (exp(mel * (2.302585092994045684 / 2595.0)) - 1.0);  // 10^x = e^{x ln10}
        bins[t] = floor((double)(NFFT + 1) * hz / (double)SR);
    }
    __syncthreads();

    for (int n = g; n < WIN; n += ng)
        d_window[n] = 0.54f - 0.46f * cosf((float)(2.0 * M_PI / (double)WIN) * (float)n);

    for (int i = g; i < NMELS * 33; i += ng) {
        int r = i / 33, j = i - r * 33;
        int lo = (int)bins[r], c = (int)bins[r + 1], hi = (int)bins[r + 2];
        int k = lo + j;
        float w = 0.0f;
        if (k < c)       w = (float)(k - lo) / (float)(c - lo);
        else if (k < hi) w = (float)(hi - k) / (float)(hi - c);
        d_fbw[i] = w;
    }
    if (g < NMELS) {
        int lo = (int)bins[g], hi = (int)bins[g + 2];
        d_klo[g] = lo;
        int len = hi - lo;
        d_flen[g] = len > 33 ? 33 : len;      // max actual width is 31
    }
    for (int i = g; i < NDCT * 41; i += ng) {
        int k = i / 41, n = i - k * 41;
        float val = 0.0f;
        if (n < NMELS) {
            float arg = (float)(M_PI / 80.0) * (float)(k * (2 * n + 1));
            float sc = (k == 0) ? 0.158113883008419f : 0.223606797749979f; // sqrt(1/40), sqrt(2/40)
            val = sc * cosf(arg);
        }
        d_dct16[i] = val;
    }
}

// ---------------- complex helpers ----------------
__device__ __forceinline__ float2 cadd(float2 a, float2 b) { return make_float2(a.x + b.x, a.y + b.y); }
__device__ __forceinline__ float2 csub(float2 a, float2 b) { return make_float2(a.x - b.x, a.y - b.y); }
__device__ __forceinline__ float2 cmul(float2 a, float2 b) {
    return make_float2(a.x * b.x - a.y * b.y, a.x * b.y + a.y * b.x);
}
__device__ __forceinline__ float2 negi(float2 a) { return make_float2(a.y, -a.x); }  // -i*a

__device__ __forceinline__ void dft8(float2 v[8]) {
    const float c = 0.70710678118654752f;
    float2 t0 = cadd(v[0], v[4]), t1 = csub(v[0], v[4]);
    float2 t2 = cadd(v[2], v[6]), t3 = csub(v[2], v[6]);
    float2 E0 = cadd(t0, t2), E2 = csub(t0, t2);
    float2 t3n = negi(t3);
    float2 E1 = cadd(t1, t3n), E3 = csub(t1, t3n);
    float2 u0 = cadd(v[1], v[5]), u1 = csub(v[1], v[5]);
    float2 u2 = cadd(v[3], v[7]), u3 = csub(v[3], v[7]);
    float2 O0 = cadd(u0, u2), O2 = csub(u0, u2);
    float2 u3n = negi(u3);
    float2 O1 = cadd(u1, u3n), O3 = csub(u1, u3n);
    O1 = make_float2(c * (O1.x + O1.y), c * (O1.y - O1.x));
    O2 = negi(O2);
    O3 = make_float2(c * (O3.y - O3.x), -c * (O3.x + O3.y));
    v[0] = cadd(E0, O0); v[4] = csub(E0, O0);
    v[1] = cadd(E1, O1); v[5] = csub(E1, O1);
    v[2] = cadd(E2, O2); v[6] = csub(E2, O2);
    v[3] = cadd(E3, O3); v[7] = csub(E3, O3);
}

// ---------------- main kernel: one frame-pair per 64-thread group, 4 groups/CTA ----------------
__global__ __launch_bounds__(THREADS, 5) void mfcc_kernel(const float* __restrict__ x,
                                                          float* __restrict__ out) {
    __shared__ float2 sZ[GROUPS][568];            // FFT exchange buffer; mag overlay
    __shared__ float  sMel[GROUPS][2][NMELS];
    __shared__ float  sMfcc[GROUPS][2][NDCT];
    __shared__ float  sD1[GROUPS][2][NDCT];
    __shared__ float  sFbw[NMELS * 33];
    __shared__ int    sKlo[NMELS];
    __shared__ int    sLen[NMELS];
    __shared__ float  sDct[NDCT * 41];

    const int tid = threadIdx.x;
    const int lt  = tid & 63;
    const int grp = tid >> 6;
    const int p   = blockIdx.x * GROUPS + grp;    // packed-pair id (grid exact)
    const int b   = p / (NF / 2);
    const int fp  = p - b * (NF / 2);
    const int f0  = 2 * fp;
    const size_t row = (size_t)b * LEN;
    const int base0 = f0 * HOP;

    // cooperative table staging (coalesced), CTA-wide — amortized over 4 groups
    for (int i = tid; i < NMELS * 33; i += THREADS) sFbw[i] = d_fbw[i];
    for (int i = tid; i < NDCT * 41;  i += THREADS) sDct[i] = d_dct16[i];
    if (tid < NMELS) { sKlo[tid] = d_klo[tid]; sLen[tid] = d_flen[tid]; }

    float2 v[8];

    // ---- load + pre-emphasis + window (direct dual LDG; coalesced & line-shared) ----
    #pragma unroll
    for (int j = 0; j < 8; j++) {
        int n = lt + 64 * j;
        if (n < WIN) {
            float w = d_window[n];
            int i0 = base0 + n;
            float a0 = x[row + i0];
            float p0 = (i0 == 0) ? a0 : (a0 - 0.97f * x[row + i0 - 1]);
            int i1 = i0 + HOP;
            float a1 = x[row + i1];
            float p1 = a1 - 0.97f * x[row + i1 - 1];
            v[j] = make_float2(p0 * w, p1 * w);
        } else {
            v[j] = make_float2(0.0f, 0.0f);
        }
    }
    __syncthreads();   // tables staged + sZ free

    // ---- stage 1: radix-8 over stride 64, twiddle W512^(t*s) via sincos powers ----
    dft8(v);
    {
        float sv, cv;
        __sincosf(-0.01227184630308513f * (float)lt, &sv, &cv);   // -2*pi/512 * lt
        float2 w1 = make_float2(cv, sv);
        float2 w = w1;
        v[1] = cmul(v[1], w);
        #pragma unroll
        for (int s = 2; s < 8; s++) { w = cmul(w, w1); v[s] = cmul(v[s], w); }
    }

    // exchange 1: store z_s[t] at 72*s + t ; read z_s[n'' + 8j']
    #pragma unroll
    for (int s = 0; s < 8; s++) sZ[grp][72 * s + lt] = v[s];
    __syncthreads();
    {
        const int s = lt >> 3, npp = lt & 7;
        #pragma unroll
        for (int j = 0; j < 8; j++) v[j] = sZ[grp][72 * s + npp + 8 * j];
        __syncthreads();

        // ---- stage 2: radix-8, twiddle W64^(n''*s') ----
        dft8(v);
        {
            float sv, cv;
            __sincosf(-0.0981747704246810f * (float)npp, &sv, &cv); // -2*pi/64 * npp
            float2 w1 = make_float2(cv, sv);
            float2 w = w1;
            v[1] = cmul(v[1], w);
            #pragma unroll
            for (int sp = 2; sp < 8; sp++) { w = cmul(w, w1); v[sp] = cmul(v[sp], w); }
        }

        // exchange 2: store at 68*n'' + 8*s' + s (bank-bijective per half-warp)
        #pragma unroll
        for (int sp = 0; sp < 8; sp++) sZ[grp][68 * npp + 8 * sp + s] = v[sp];
    }
    __syncthreads();
    {
        const int sp = lt >> 3, s = lt & 7;       // outputs X[64m + 8sp + s] = X[64m + lt]
        #pragma unroll
        for (int j = 0; j < 8; j++) v[j] = sZ[grp][68 * j + 8 * sp + s];
        __syncthreads();

        // ---- stage 3: radix-8 -> store X flat at slot 64*m + lt ----
        dft8(v);
        #pragma unroll
        for (int m = 0; m < 8; m++) sZ[grp][64 * m + lt] = v[m];
    }
    __syncthreads();

    // ---- conjugate-symmetry unpack into registers, then compact stride-1 store ----
    float m0[4], m1[4];
    #pragma unroll
    for (int j = 0; j < 4; j++) {
        int k  = lt + 64 * j;                     // 0..255
        int kk = (NFFT - k) & (NFFT - 1);
        float2 u = sZ[grp][k];
        float2 w = sZ[grp][kk];
        float Ar = 0.5f * (u.x + w.x), Ai = 0.5f * (u.y - w.y);
        float Br = 0.5f * (u.y + w.y), Bi = 0.5f * (w.x - u.x);
        m0[j] = sqrtf(Ar * Ar + Ai * Ai);
        m1[j] = sqrtf(Br * Br + Bi * Bi);
    }
    float e0 = 0.0f, e1 = 0.0f;
    if (lt == 0) {                                // k = 256 (Nyquist)
        float2 u = sZ[grp][256];
        e0 = fabsf(u.x); e1 = fabsf(u.y);
    }
    __syncthreads();                              // all spectrum reads done
    float* __restrict__ sMagF = (float*)sZ[grp];  // overlay: mag0 at [k], mag1 at [264+k]
    #pragma unroll
    for (int j = 0; j < 4; j++) {
        int k = lt + 64 * j;
        sMagF[k] = m0[j];
        sMagF[MAGSTRIDE + k] = m1[j];
    }
    if (lt == 0) { sMagF[256] = e0; sMagF[MAGSTRIDE + 256] = e1; }
    __syncthreads();

    // ---- mel filterbank + log (80 tasks over 64 threads), variable-length ----
    #pragma unroll
    for (int i = lt; i < 2 * NMELS; i += 64) {
        int fr = i / NMELS, m = i - fr * NMELS;
        const int klo = sKlo[m], len = sLen[m];
        const float* __restrict__ fw = sFbw + m * 33;
        const float* __restrict__ mg = sMagF + fr * MAGSTRIDE + klo;
        float acc = 0.0f;
        for (int j = 0; j < len; j++) acc = fmaf(fw[j], mg[j], acc);
        sMel[grp][fr][m] = __logf(acc + 1e-20f);
    }
    __syncthreads();

    // ---- DCT-II ortho, 16 rows, split dot across thread pairs ----
    {
        int task = lt >> 1;                       // 0..31 = (fr, m)
        int half = lt & 1;
        int fr = task >> 4, m = task & 15;
        const float* __restrict__ dr = sDct + m * 41 + half * 20;
        const float* __restrict__ ml = sMel[grp][fr] + half * 20;
        float acc = 0.0f;
        #pragma unroll
        for (int n = 0; n < 20; n++) acc = fmaf(dr[n], ml[n], acc);
        acc += __shfl_xor_sync(0xffffffffu, acc, 1);
        if (half == 0) sMfcc[grp][fr][m] = acc;
    }
    __syncthreads();

    // ---- first delta over coefficients (valid for c<=14; we need c<=13) ----
    if (lt < 32) {
        int fr = lt >> 4, c = lt & 15;
        float val = 0.0f;
        if (c >= 1 && c <= 14) val = 0.5f * (sMfcc[grp][fr][c + 1] - sMfcc[grp][fr][c - 1]);
        sD1[grp][fr][c] = val;
    }
    __syncthreads();

    // ---- write [mfcc[0:13], d1[0:13], d2[0:13]] for both frames ----
    #pragma unroll
    for (int i = lt; i < 2 * OUTC; i += 64) {
        int fr = i / OUTC, c = i - fr * OUTC;
        int frame = b * NF + f0 + fr;
        float val;
        if (c < NMFCC) {
            val = sMfcc[grp][fr][c];
        } else if (c < 2 * NMFCC) {
            val = sD1[grp][fr][c - NMFCC];
        } else {
            int cc = c - 2 * NMFCC;
            val = (cc >= 1) ? 0.5f * (sD1[grp][fr][cc + 1] - sD1[grp][fr][cc - 1]) : 0.0f;
        }
        out[(size_t)frame * OUTC + c] = val;
    }
}

extern "C" void kernel_launch(void* const* d_in, const int* in_sizes, int n_in,
                              void* d_out, int out_size) {
    (void)in_sizes; (void)n_in; (void)out_size;
    const float* x = (const float*)d_in[0];
    float* out = (float*)d_out;
    init_consts_kernel<<<8, 128>>>();
    mfcc_kernel<<<NPAIR / GROUPS, THREADS>>>(x, out);
}